// round 2
// baseline (speedup 1.0000x reference)
#include <cuda_runtime.h>

// Problem constants
#define B_    8
#define C_    64
#define N_    4096
#define K_    16
#define OUT_  64
#define R_    128   // 2*OUT virtual rows: [0,64) = u (=(W1-W2)x + bias), [64,128) = v (=W2 x)

// Scratch (device globals — no allocation allowed)
__device__ float g_wt[C_ * R_];               // Wt[c*128 + r] : transposed combined weights
__device__ float g_uv[B_ * N_ * R_];          // [b][n][r], node-major 512B rows

// ---------------------------------------------------------------------------
// Kernel 0: build combined transposed weight matrix
//   r <  64 : Wd[r][c] = W[r][c] - W[r][64+c]      (multiplies center x_i)
//   r >= 64 : W2[r-64][c] = W[r-64][64+c]           (multiplies neighbor x_j)
// stored as Wt[c*128 + r] for coalesced loads in the GEMM.
// ---------------------------------------------------------------------------
__global__ void prep_w(const float* __restrict__ W) {
    int t = blockIdx.x * blockDim.x + threadIdx.x;   // 0..8191
    if (t >= C_ * R_) return;
    int r = t & 127;
    int c = t >> 7;
    float v;
    if (r < 64) v = W[r * 128 + c] - W[r * 128 + 64 + c];
    else        v = W[(r - 64) * 128 + 64 + c];
    g_wt[t] = v;   // t == c*128 + r  -> coalesced store
}

// ---------------------------------------------------------------------------
// Kernel 1: per-node GEMM  uv[b][n][r] = sum_c Wt[c][r] * x[b][c][n]  (+bias for r<64)
// Block: 256 threads, tile = 128 rows x 64 nodes. Thread computes 8x4 register tile.
// Shared: sW 64x128 (32KB) + sX 64x64 (16KB) = 48KB.
// ---------------------------------------------------------------------------
__global__ void __launch_bounds__(256) gemm_uv(const float* __restrict__ x,
                                               const float* __restrict__ bias) {
    __shared__ float sW[C_][R_];   // [c][r]
    __shared__ float sX[C_][64];   // [c][n_local]

    const int b  = blockIdx.y;
    const int n0 = blockIdx.x * 64;
    const int t  = threadIdx.x;

    // Load weights (coalesced: consecutive lin -> consecutive r within a c-row)
    for (int lin = t; lin < C_ * R_; lin += 256)
        ((float*)sW)[lin] = g_wt[lin];

    // Load x tile: x[b][c][n0+nl], consecutive nl coalesced
    for (int lin = t; lin < C_ * 64; lin += 256) {
        int c  = lin >> 6;
        int nl = lin & 63;
        sX[c][nl] = x[((b * C_ + c) * N_) + n0 + nl];
    }
    __syncthreads();

    const int tr = t & 15;   // row group base (r = tr + 16*i)
    const int tc = t >> 4;   // node group base (n = tc + 16*j)

    float acc[8][4];
    #pragma unroll
    for (int i = 0; i < 8; i++) {
        int r = tr + 16 * i;
        float binit = (r < 64) ? bias[r] : 0.0f;
        #pragma unroll
        for (int j = 0; j < 4; j++) acc[i][j] = binit;
    }

    #pragma unroll 4
    for (int c = 0; c < 64; c++) {
        float w[8], xv[4];
        #pragma unroll
        for (int i = 0; i < 8; i++) w[i] = sW[c][tr + 16 * i];   // conflict-free
        #pragma unroll
        for (int j = 0; j < 4; j++) xv[j] = sX[c][tc + 16 * j];  // conflict-free
        #pragma unroll
        for (int i = 0; i < 8; i++)
            #pragma unroll
            for (int j = 0; j < 4; j++)
                acc[i][j] = fmaf(w[i], xv[j], acc[i][j]);
    }

    // Write node-major rows of 128 floats (512B per node)
    const int base = (b * N_ + n0) * R_;
    #pragma unroll
    for (int j = 0; j < 4; j++) {
        int n = tc + 16 * j;
        #pragma unroll
        for (int i = 0; i < 8; i++) {
            int r = tr + 16 * i;
            g_uv[base + n * R_ + r] = acc[i][j];
        }
    }
}

// ---------------------------------------------------------------------------
// Kernel 2: out[b][o][n] = max_k relu( u[b][i1(k)][o] + v[b][i0(k)][o] )
// One warp per node (8 nodes / block). Edge indices loaded once, shfl-broadcast.
// Each lane handles o = 2*lane, 2*lane+1 via float2 gathers (2 sectors/gather).
// Output transposed through SMEM for sector-aligned stores.
// edge_index is int32 (JAX downcasts jnp.int64 -> int32 without x64 mode).
// ---------------------------------------------------------------------------
__global__ void __launch_bounds__(256) gather_max(const int* __restrict__ edge,
                                                  float* __restrict__ out) {
    __shared__ float sm[OUT_][9];   // pad 8->9 to dodge bank conflicts

    const int b    = blockIdx.y;
    const int n0   = blockIdx.x * 8;
    const int w    = threadIdx.x >> 5;
    const int lane = threadIdx.x & 31;
    const int n    = n0 + w;

    // lanes 0..15: edge_index[0][b][n][k] (neighbors -> v), lanes 16..31: edge_index[1] (centers -> u)
    const int s = lane >> 4;
    const int k = lane & 15;
    const int idx = edge[((s * B_ + b) * N_ + n) * K_ + k] & (N_ - 1); // mask: trap-proof, no-op for valid data

    const float* uvb = g_uv + (size_t)b * N_ * R_;

    float m0 = 0.0f, m1 = 0.0f;   // relu(y) >= 0, so init 0 == max over relu
    #pragma unroll
    for (int kk = 0; kk < K_; kk++) {
        int i0 = __shfl_sync(0xffffffffu, idx, kk);        // neighbor index
        int i1 = __shfl_sync(0xffffffffu, idx, kk + 16);   // center index
        const float2 au = ((const float2*)(uvb + i1 * R_))[lane];        // u[i1][2l..2l+1]
        const float2 av = ((const float2*)(uvb + i0 * R_ + 64))[lane];   // v[i0][2l..2l+1]
        m0 = fmaxf(m0, au.x + av.x);
        m1 = fmaxf(m1, au.y + av.y);
    }

    sm[2 * lane][w]     = m0;
    sm[2 * lane + 1][w] = m1;
    __syncthreads();

    const int t = threadIdx.x;
    #pragma unroll
    for (int it = 0; it < 2; it++) {
        int lin = t + it * 256;        // 512 values: 64 o x 8 n
        int o   = lin >> 3;
        int nl  = lin & 7;
        out[((b * OUT_ + o) * N_) + n0 + nl] = sm[o][nl];
    }
}

// ---------------------------------------------------------------------------
extern "C" void kernel_launch(void* const* d_in, const int* in_sizes, int n_in,
                              void* d_out, int out_size) {
    const float* x    = (const float*)d_in[0];
    const int*   edge = (const int*)d_in[1];
    const float* W    = (const float*)d_in[2];
    const float* bias = (const float*)d_in[3];
    float*       out  = (float*)d_out;

    prep_w<<<(C_ * R_ + 255) / 256, 256>>>(W);

    dim3 g1(N_ / 64, B_);
    gemm_uv<<<g1, 256>>>(x, bias);

    dim3 g2(N_ / 8, B_);
    gather_max<<<g2, 256>>>(edge, out);
}

// round 3
// speedup vs baseline: 1.0437x; 1.0437x over previous
#include <cuda_runtime.h>
#include <cuda_fp16.h>

// Problem constants
#define B_    8
#define C_    64
#define N_    4096
#define K_    16
#define OUT_  64
#define R_    128   // 2*OUT rows: [0,64) = u (=(W1-W2)x + bias), [64,128) = v (=W2 x)

// Scratch (device globals — no allocation allowed)
__device__ float  g_wt[C_ * R_];                 // Wt[c*128 + r] : transposed combined weights (fp32)
__device__ __half g_uvh[B_ * N_ * R_];           // [b][n][r] as half: row = 256B = [u 0..63 | v 0..63]

// ---------------------------------------------------------------------------
// Kernel 0: build combined transposed weight matrix (fp32)
//   r <  64 : Wd[r][c] = W[r][c] - W[r][64+c]      (multiplies center x_i)
//   r >= 64 : W2[r-64][c] = W[r-64][64+c]          (multiplies neighbor x_j)
// stored as Wt[c*128 + r] for conflict-free smem loads in the GEMM.
// ---------------------------------------------------------------------------
__global__ void prep_w(const float* __restrict__ W) {
    int t = blockIdx.x * blockDim.x + threadIdx.x;   // 0..8191
    int r = t & 127;
    int c = t >> 7;
    float v;
    if (r < 64) v = W[r * 128 + c] - W[r * 128 + 64 + c];
    else        v = W[(r - 64) * 128 + 64 + c];
    g_wt[t] = v;   // t == c*128 + r  -> coalesced store
}

// ---------------------------------------------------------------------------
// Kernel 1: uv[b][n][r] = sum_c Wt[c][r] * x[b][c][n]  (+bias for r<64), stored fp16.
// Block: 256 threads, tile = 128 rows x 64 nodes. Thread computes 8x4 register tile.
// fp32 accumulate, half store (node row = 256B).
// ---------------------------------------------------------------------------
__global__ void __launch_bounds__(256) gemm_uv(const float* __restrict__ x,
                                               const float* __restrict__ bias) {
    __shared__ float sW[C_][R_];   // [c][r]  32KB
    __shared__ float sX[C_][64];   // [c][nl] 16KB

    const int b  = blockIdx.y;
    const int n0 = blockIdx.x * 64;
    const int t  = threadIdx.x;

    for (int lin = t; lin < C_ * R_; lin += 256)
        ((float*)sW)[lin] = g_wt[lin];

    for (int lin = t; lin < C_ * 64; lin += 256) {
        int c  = lin >> 6;
        int nl = lin & 63;
        sX[c][nl] = x[((b * C_ + c) * N_) + n0 + nl];
    }
    __syncthreads();

    const int tr = t & 15;   // r = tr + 16*i
    const int tc = t >> 4;   // n = tc + 16*j

    float acc[8][4];
    #pragma unroll
    for (int i = 0; i < 8; i++) {
        int r = tr + 16 * i;
        float binit = (r < 64) ? bias[r] : 0.0f;
        #pragma unroll
        for (int j = 0; j < 4; j++) acc[i][j] = binit;
    }

    #pragma unroll 4
    for (int c = 0; c < 64; c++) {
        float w[8], xv[4];
        #pragma unroll
        for (int i = 0; i < 8; i++) w[i] = sW[c][tr + 16 * i];   // conflict-free
        #pragma unroll
        for (int j = 0; j < 4; j++) xv[j] = sX[c][tc + 16 * j];  // conflict-free
        #pragma unroll
        for (int i = 0; i < 8; i++)
            #pragma unroll
            for (int j = 0; j < 4; j++)
                acc[i][j] = fmaf(w[i], xv[j], acc[i][j]);
    }

    // Store half: row of 128 halves per node (256B). slot == r for both halves.
    __half* outb = g_uvh + (size_t)(b * N_ + n0) * R_;
    #pragma unroll
    for (int j = 0; j < 4; j++) {
        int n = tc + 16 * j;
        #pragma unroll
        for (int i = 0; i < 8; i++) {
            int r = tr + 16 * i;
            outb[n * R_ + r] = __float2half_rn(acc[i][j]);
        }
    }
}

// ---------------------------------------------------------------------------
// Kernel 2: out[b][o][n] = max_k relu( u[b][i1(k)][o] + v[b][i0(k)][o] )
// One warp per node. Edge indices loaded once, shfl-broadcast.
// Each lane handles o = 2*lane, 2*lane+1 via half2 gathers:
//   u gather = 32 lanes x 4B = one 128B line; v gather likewise.
// Output transposed through SMEM for sector-aligned fp32 stores.
// ---------------------------------------------------------------------------
__global__ void __launch_bounds__(256) gather_max(const int* __restrict__ edge,
                                                  float* __restrict__ out) {
    __shared__ float sm[OUT_][9];   // pad 8->9 to dodge bank conflicts

    const int b    = blockIdx.y;
    const int n0   = blockIdx.x * 8;
    const int w    = threadIdx.x >> 5;
    const int lane = threadIdx.x & 31;
    const int n    = n0 + w;

    // lanes 0..15: edge_index[0] (neighbors -> v), lanes 16..31: edge_index[1] (centers -> u)
    const int s = lane >> 4;
    const int k = lane & 15;
    const int idx = edge[((s * B_ + b) * N_ + n) * K_ + k] & (N_ - 1);

    const __half* uvb = g_uvh + (size_t)b * N_ * R_;

    float m0 = 0.0f, m1 = 0.0f;   // relu(y) >= 0 -> init 0 == max over relu
    #pragma unroll
    for (int kk = 0; kk < K_; kk++) {
        int i0 = __shfl_sync(0xffffffffu, idx, kk);        // neighbor
        int i1 = __shfl_sync(0xffffffffu, idx, kk + 16);   // center
        __half2 hu = ((const __half2*)(uvb + i1 * R_))[lane];        // u[2l..2l+1]
        __half2 hv = ((const __half2*)(uvb + i0 * R_ + 64))[lane];   // v[2l..2l+1]
        float2 fu = __half22float2(hu);
        float2 fv = __half22float2(hv);
        m0 = fmaxf(m0, fu.x + fv.x);
        m1 = fmaxf(m1, fu.y + fv.y);
    }

    sm[2 * lane][w]     = m0;
    sm[2 * lane + 1][w] = m1;
    __syncthreads();

    const int t = threadIdx.x;
    #pragma unroll
    for (int it = 0; it < 2; it++) {
        int lin = t + it * 256;        // 512 values: 64 o x 8 n
        int o   = lin >> 3;
        int nl  = lin & 7;
        out[((b * OUT_ + o) * N_) + n0 + nl] = sm[o][nl];
    }
}

// ---------------------------------------------------------------------------
extern "C" void kernel_launch(void* const* d_in, const int* in_sizes, int n_in,
                              void* d_out, int out_size) {
    const float* x    = (const float*)d_in[0];
    const int*   edge = (const int*)d_in[1];
    const float* W    = (const float*)d_in[2];
    const float* bias = (const float*)d_in[3];
    float*       out  = (float*)d_out;

    prep_w<<<8, 1024>>>(W);

    dim3 g1(N_ / 64, B_);
    gemm_uv<<<g1, 256>>>(x, bias);

    dim3 g2(N_ / 8, B_);
    gather_max<<<g2, 256>>>(edge, out);
}

// round 4
// speedup vs baseline: 1.2022x; 1.1519x over previous
#include <cuda_runtime.h>
#include <cuda_fp16.h>

// Problem constants
#define B_    8
#define C_    64
#define N_    4096
#define K_    16
#define OUT_  64
#define R_    128   // 2*OUT rows: [0,64) = u (=(W1-W2)x + bias), [64,128) = v (=W2 x)

// Scratch (device globals — no allocation allowed)
__device__ float  g_wt[C_ * R_];                 // Wt[c*128 + r] : transposed combined weights (fp32)
__device__ __half g_uvh[B_ * N_ * R_];           // [b][n][r] as half: row = 256B = [u 0..63 | v 0..63]

// ---- packed f32x2 helpers (sm_100+ PTX) ------------------------------------
__device__ __forceinline__ unsigned long long pack2(float lo, float hi) {
    unsigned long long r;
    asm("mov.b64 %0, {%1, %2};" : "=l"(r) : "f"(lo), "f"(hi));
    return r;
}
__device__ __forceinline__ void unpack2(unsigned long long v, float& lo, float& hi) {
    asm("mov.b64 {%0, %1}, %2;" : "=f"(lo), "=f"(hi) : "l"(v));
}
__device__ __forceinline__ void ffma2(unsigned long long& d,
                                      unsigned long long a,
                                      unsigned long long b) {
    asm("fma.rn.f32x2 %0, %1, %2, %0;" : "+l"(d) : "l"(a), "l"(b));
}

// ---------------------------------------------------------------------------
// Kernel 0: build combined transposed weight matrix (fp32)
//   r <  64 : Wd[r][c] = W[r][c] - W[r][64+c]      (multiplies center x_i)
//   r >= 64 : W2[r-64][c] = W[r-64][64+c]          (multiplies neighbor x_j)
// stored as Wt[c*128 + r].
// ---------------------------------------------------------------------------
__global__ void prep_w(const float* __restrict__ W) {
    int t = blockIdx.x * blockDim.x + threadIdx.x;   // 0..8191
    int r = t & 127;
    int c = t >> 7;
    float v;
    if (r < 64) v = W[r * 128 + c] - W[r * 128 + 64 + c];
    else        v = W[(r - 64) * 128 + 64 + c];
    g_wt[t] = v;
}

// ---------------------------------------------------------------------------
// Kernel 1: uv[b][n][r] = sum_c Wt[c][r] * x[b][c][n] (+bias r<64), fp16 store.
// 256 threads, tile 128r x 64n. Thread: 4 r-pairs x 4 nodes via fma.rn.f32x2.
//   tr = t&15, tc = t>>4
//   r-pair i2: (2tr + 32*i2, 2tr + 32*i2 + 1)   -> LDS.64 of sW, conflict-free
//   n: 4*tc + j                                  -> LDS.128 of sX, broadcast
// ---------------------------------------------------------------------------
__global__ void __launch_bounds__(256) gemm_uv(const float* __restrict__ x,
                                               const float* __restrict__ bias) {
    __shared__ float sW[C_][R_];   // [c][r]  32KB
    __shared__ float sX[C_][64];   // [c][nl] 16KB

    const int b  = blockIdx.y;
    const int n0 = blockIdx.x * 64;
    const int t  = threadIdx.x;

    for (int lin = t; lin < C_ * R_; lin += 256)
        ((float*)sW)[lin] = g_wt[lin];                 // linear copy, coalesced

    for (int lin = t; lin < C_ * 64; lin += 256) {
        int c  = lin >> 6;
        int nl = lin & 63;
        sX[c][nl] = x[((b * C_ + c) * N_) + n0 + nl];
    }
    __syncthreads();

    const int tr = t & 15;
    const int tc = t >> 4;
    const int rb = 2 * tr;     // base r of pair 0

    unsigned long long acc[4][4];
    #pragma unroll
    for (int i2 = 0; i2 < 4; i2++) {
        unsigned long long binit;
        if (i2 < 2) {                     // u rows: r = rb+32*i2 in [0,64)
            const float2 bp = *(const float2*)&bias[rb + 32 * i2];
            binit = pack2(bp.x, bp.y);
        } else {
            binit = 0ull;                 // v rows
        }
        #pragma unroll
        for (int j = 0; j < 4; j++) acc[i2][j] = binit;
    }

    #pragma unroll 4
    for (int c = 0; c < 64; c++) {
        unsigned long long w2[4];
        #pragma unroll
        for (int i2 = 0; i2 < 4; i2++)
            w2[i2] = *(const unsigned long long*)&sW[c][rb + 32 * i2];  // LDS.64
        const float4 xq = *(const float4*)&sX[c][4 * tc];                // LDS.128 bcast
        unsigned long long x2[4];
        x2[0] = pack2(xq.x, xq.x);
        x2[1] = pack2(xq.y, xq.y);
        x2[2] = pack2(xq.z, xq.z);
        x2[3] = pack2(xq.w, xq.w);
        #pragma unroll
        for (int i2 = 0; i2 < 4; i2++)
            #pragma unroll
            for (int j = 0; j < 4; j++)
                ffma2(acc[i2][j], w2[i2], x2[j]);
    }

    // Store fp16: node row = 128 halves [u | v]; pair -> one half2 (4B) store.
    __half* outb = g_uvh + (size_t)(b * N_ + n0) * R_;
    #pragma unroll
    for (int j = 0; j < 4; j++) {
        const int n = 4 * tc + j;
        #pragma unroll
        for (int i2 = 0; i2 < 4; i2++) {
            float lo, hi;
            unpack2(acc[i2][j], lo, hi);
            *(__half2*)(outb + n * R_ + rb + 32 * i2) = __floats2half2_rn(lo, hi);
        }
    }
}

// ---------------------------------------------------------------------------
// Kernel 2: out[b][o][n] = max_k relu( u[b][i1(k)][o] + v[b][i0(k)][o] )
// One warp per node; shfl-broadcast indices; half2 gathers (1 line/warp/load).
// ---------------------------------------------------------------------------
__global__ void __launch_bounds__(256) gather_max(const int* __restrict__ edge,
                                                  float* __restrict__ out) {
    __shared__ float sm[OUT_][9];

    const int b    = blockIdx.y;
    const int n0   = blockIdx.x * 8;
    const int w    = threadIdx.x >> 5;
    const int lane = threadIdx.x & 31;
    const int n    = n0 + w;

    const int s = lane >> 4;
    const int k = lane & 15;
    const int idx = edge[((s * B_ + b) * N_ + n) * K_ + k] & (N_ - 1);

    const __half* uvb = g_uvh + (size_t)b * N_ * R_;

    float m0 = 0.0f, m1 = 0.0f;
    #pragma unroll
    for (int kk = 0; kk < K_; kk++) {
        int i0 = __shfl_sync(0xffffffffu, idx, kk);        // neighbor -> v
        int i1 = __shfl_sync(0xffffffffu, idx, kk + 16);   // center   -> u
        __half2 hu = ((const __half2*)(uvb + i1 * R_))[lane];
        __half2 hv = ((const __half2*)(uvb + i0 * R_ + 64))[lane];
        float2 fu = __half22float2(hu);
        float2 fv = __half22float2(hv);
        m0 = fmaxf(m0, fu.x + fv.x);
        m1 = fmaxf(m1, fu.y + fv.y);
    }

    sm[2 * lane][w]     = m0;
    sm[2 * lane + 1][w] = m1;
    __syncthreads();

    const int t = threadIdx.x;
    #pragma unroll
    for (int it = 0; it < 2; it++) {
        int lin = t + it * 256;
        int o   = lin >> 3;
        int nl  = lin & 7;
        out[((b * OUT_ + o) * N_) + n0 + nl] = sm[o][nl];
    }
}

// ---------------------------------------------------------------------------
extern "C" void kernel_launch(void* const* d_in, const int* in_sizes, int n_in,
                              void* d_out, int out_size) {
    const float* x    = (const float*)d_in[0];
    const int*   edge = (const int*)d_in[1];
    const float* W    = (const float*)d_in[2];
    const float* bias = (const float*)d_in[3];
    float*       out  = (float*)d_out;

    prep_w<<<32, 256>>>(W);

    dim3 g1(N_ / 64, B_);
    gemm_uv<<<g1, 256>>>(x, bias);

    dim3 g2(N_ / 8, B_);
    gather_max<<<g2, 256>>>(edge, out);
}

// round 5
// speedup vs baseline: 1.2189x; 1.0138x over previous
#include <cuda_runtime.h>
#include <cuda_fp16.h>

// Problem constants
#define B_    8
#define C_    64
#define N_    4096
#define K_    16
#define OUT_  64
#define R_    128   // 2*OUT rows: [0,64) = u (=(W1-W2)x + bias), [64,128) = v (=W2 x)

#define SW_STRIDE 130   // even (8B-aligned pairs) and ≡2 mod 32 (2-way STS conflict max)
#define SMEM_BYTES ((C_ * SW_STRIDE + C_ * 64) * 4)   // 49,664 B

// Scratch (device global — no allocation allowed)
__device__ __half g_uvh[B_ * N_ * R_];   // [b][n][r] half: row = 256B = [u 0..63 | v 0..63]

// ---- packed f32x2 helpers (sm_100+ PTX) ------------------------------------
__device__ __forceinline__ unsigned long long pack2(float lo, float hi) {
    unsigned long long r;
    asm("mov.b64 %0, {%1, %2};" : "=l"(r) : "f"(lo), "f"(hi));
    return r;
}
__device__ __forceinline__ void unpack2(unsigned long long v, float& lo, float& hi) {
    asm("mov.b64 {%0, %1}, %2;" : "=f"(lo), "=f"(hi) : "l"(v));
}
__device__ __forceinline__ void ffma2(unsigned long long& d,
                                      unsigned long long a,
                                      unsigned long long b) {
    asm("fma.rn.f32x2 %0, %1, %2, %0;" : "+l"(d) : "l"(a), "l"(b));
}

// ---------------------------------------------------------------------------
// Kernel 1: uv[b][n][r] = sum_c Wt[c][r] * x[b][c][n] (+bias r<64), fp16 store.
// Weight transform fused into the load phase (W is L2-resident after block 0):
//   Wt[c][r]    = W[r][c] - W[r][64+c]   (u rows)
//   Wt[c][r+64] = W[r][64+c]             (v rows)
// 256 threads, tile 128r x 64n. Thread: 4 r-pairs x 4 nodes via fma.rn.f32x2.
// ---------------------------------------------------------------------------
__global__ void __launch_bounds__(256) gemm_uv(const float* __restrict__ x,
                                               const float* __restrict__ W,
                                               const float* __restrict__ bias) {
    extern __shared__ float dsm[];
    float (*sW)[SW_STRIDE] = (float (*)[SW_STRIDE])dsm;          // [c][r] padded
    float (*sX)[64]        = (float (*)[64])(dsm + C_ * SW_STRIDE);

    const int b  = blockIdx.y;
    const int n0 = blockIdx.x * 64;
    const int t  = threadIdx.x;

    // Fused weight transform: coalesced LDG (c fast), 2-way-conflict STS transpose.
    for (int lin = t; lin < C_ * OUT_; lin += 256) {
        int c = lin & 63;
        int r = lin >> 6;                 // 0..63
        float a  = W[r * 128 + c];        // W1[r][c]
        float bb = W[r * 128 + 64 + c];   // W2[r][c]
        sW[c][r]      = a - bb;
        sW[c][r + 64] = bb;
    }

    for (int lin = t; lin < C_ * 64; lin += 256) {
        int c  = lin >> 6;
        int nl = lin & 63;
        sX[c][nl] = x[((b * C_ + c) * N_) + n0 + nl];
    }
    __syncthreads();

    const int tr = t & 15;
    const int tc = t >> 4;
    const int rb = 2 * tr;     // base r of pair 0

    unsigned long long acc[4][4];
    #pragma unroll
    for (int i2 = 0; i2 < 4; i2++) {
        unsigned long long binit;
        if (i2 < 2) {                     // u rows: r = rb+32*i2 in [0,64)
            const float2 bp = *(const float2*)&bias[rb + 32 * i2];
            binit = pack2(bp.x, bp.y);
        } else {
            binit = 0ull;                 // v rows
        }
        #pragma unroll
        for (int j = 0; j < 4; j++) acc[i2][j] = binit;
    }

    #pragma unroll 4
    for (int c = 0; c < 64; c++) {
        unsigned long long w2[4];
        #pragma unroll
        for (int i2 = 0; i2 < 4; i2++)
            w2[i2] = *(const unsigned long long*)&sW[c][rb + 32 * i2];  // LDS.64, conflict-free
        const float4 xq = *(const float4*)&sX[c][4 * tc];                // LDS.128 bcast
        unsigned long long x2[4];
        x2[0] = pack2(xq.x, xq.x);
        x2[1] = pack2(xq.y, xq.y);
        x2[2] = pack2(xq.z, xq.z);
        x2[3] = pack2(xq.w, xq.w);
        #pragma unroll
        for (int i2 = 0; i2 < 4; i2++)
            #pragma unroll
            for (int j = 0; j < 4; j++)
                ffma2(acc[i2][j], w2[i2], x2[j]);
    }

    // Store fp16: node row = 128 halves [u | v]; pair -> one half2 (4B) store.
    __half* outb = g_uvh + (size_t)(b * N_ + n0) * R_;
    #pragma unroll
    for (int j = 0; j < 4; j++) {
        const int n = 4 * tc + j;
        #pragma unroll
        for (int i2 = 0; i2 < 4; i2++) {
            float lo, hi;
            unpack2(acc[i2][j], lo, hi);
            *(__half2*)(outb + n * R_ + rb + 32 * i2) = __floats2half2_rn(lo, hi);
        }
    }
}

// ---------------------------------------------------------------------------
// Kernel 2: out[b][o][n] = max_k relu( u[b][i1(k)][o] + v[b][i0(k)][o] )
// One warp per node; shfl-broadcast indices; half2 gathers (1 line/warp/load).
// ---------------------------------------------------------------------------
__global__ void __launch_bounds__(256) gather_max(const int* __restrict__ edge,
                                                  float* __restrict__ out) {
    __shared__ float sm[OUT_][9];

    const int b    = blockIdx.y;
    const int n0   = blockIdx.x * 8;
    const int w    = threadIdx.x >> 5;
    const int lane = threadIdx.x & 31;
    const int n    = n0 + w;

    const int s = lane >> 4;
    const int k = lane & 15;
    const int idx = edge[((s * B_ + b) * N_ + n) * K_ + k] & (N_ - 1);

    const __half* uvb = g_uvh + (size_t)b * N_ * R_;

    float m0 = 0.0f, m1 = 0.0f;   // relu(y) >= 0 -> init 0 == max over relu
    #pragma unroll
    for (int kk = 0; kk < K_; kk++) {
        int i0 = __shfl_sync(0xffffffffu, idx, kk);        // neighbor -> v
        int i1 = __shfl_sync(0xffffffffu, idx, kk + 16);   // center   -> u
        __half2 hu = ((const __half2*)(uvb + i1 * R_))[lane];
        __half2 hv = ((const __half2*)(uvb + i0 * R_ + 64))[lane];
        float2 fu = __half22float2(hu);
        float2 fv = __half22float2(hv);
        m0 = fmaxf(m0, fu.x + fv.x);
        m1 = fmaxf(m1, fu.y + fv.y);
    }

    sm[2 * lane][w]     = m0;
    sm[2 * lane + 1][w] = m1;
    __syncthreads();

    const int t = threadIdx.x;
    #pragma unroll
    for (int it = 0; it < 2; it++) {
        int lin = t + it * 256;        // 512 values: 64 o x 8 n
        int o   = lin >> 3;
        int nl  = lin & 7;
        out[((b * OUT_ + o) * N_) + n0 + nl] = sm[o][nl];
    }
}

// ---------------------------------------------------------------------------
extern "C" void kernel_launch(void* const* d_in, const int* in_sizes, int n_in,
                              void* d_out, int out_size) {
    const float* x    = (const float*)d_in[0];
    const int*   edge = (const int*)d_in[1];
    const float* W    = (const float*)d_in[2];
    const float* bias = (const float*)d_in[3];
    float*       out  = (float*)d_out;

    // Host-side config, not a stream op: graph-capture safe, idempotent.
    cudaFuncSetAttribute(gemm_uv, cudaFuncAttributeMaxDynamicSharedMemorySize, SMEM_BYTES);

    dim3 g1(N_ / 64, B_);
    gemm_uv<<<g1, 256, SMEM_BYTES>>>(x, W, bias);

    dim3 g2(N_ / 8, B_);
    gather_max<<<g2, 256>>>(edge, out);
}

// round 6
// speedup vs baseline: 1.3587x; 1.1148x over previous
#include <cuda_runtime.h>
#include <cuda_fp16.h>

// Problem constants
#define B_    8
#define C_    64
#define N_    4096
#define K_    16
#define OUT_  64
#define R_    128   // 2*OUT rows: [0,64) = u (=(W1-W2)x + bias), [64,128) = v (=W2 x)

#define SW_STRIDE 130   // even (8B-aligned pairs) and ≡2 mod 32 (≤2-way STS conflict)
#define SMEM_BYTES ((C_ * SW_STRIDE + C_ * 64) * 4)   // 49,664 B

// Scratch (device global — no allocation allowed)
__device__ __half g_uvh[B_ * N_ * R_];   // [b][n][r] half: row = 256B = [u 0..63 | v 0..63]

// ---- packed f32x2 helpers (sm_100+ PTX) ------------------------------------
__device__ __forceinline__ unsigned long long pack2(float lo, float hi) {
    unsigned long long r;
    asm("mov.b64 %0, {%1, %2};" : "=l"(r) : "f"(lo), "f"(hi));
    return r;
}
__device__ __forceinline__ void unpack2(unsigned long long v, float& lo, float& hi) {
    asm("mov.b64 {%0, %1}, %2;" : "=f"(lo), "=f"(hi) : "l"(v));
}
__device__ __forceinline__ void ffma2(unsigned long long& d,
                                      unsigned long long a,
                                      unsigned long long b) {
    asm("fma.rn.f32x2 %0, %1, %2, %0;" : "+l"(d) : "l"(a), "l"(b));
}

// ---------------------------------------------------------------------------
// Kernel 1: uv[b][n][r] = sum_c Wt[c][r] * x[b][c][n] (+bias r<64), fp16 store.
// Fused weight transform; FFMA2 compute (4 r-pairs x 4 nodes per thread).
// ---------------------------------------------------------------------------
__global__ void __launch_bounds__(256) gemm_uv(const float* __restrict__ x,
                                               const float* __restrict__ W,
                                               const float* __restrict__ bias) {
    extern __shared__ float dsm[];
    float (*sW)[SW_STRIDE] = (float (*)[SW_STRIDE])dsm;          // [c][r] padded
    float (*sX)[64]        = (float (*)[64])(dsm + C_ * SW_STRIDE);

    const int b  = blockIdx.y;
    const int n0 = blockIdx.x * 64;
    const int t  = threadIdx.x;

    // Fused weight transform (W is L2-resident after the first blocks).
    for (int lin = t; lin < C_ * OUT_; lin += 256) {
        int c = lin & 63;
        int r = lin >> 6;                 // 0..63
        float a  = W[r * 128 + c];        // W1[r][c]
        float bb = W[r * 128 + 64 + c];   // W2[r][c]
        sW[c][r]      = a - bb;
        sW[c][r + 64] = bb;
    }

    for (int lin = t; lin < C_ * 64; lin += 256) {
        int c  = lin >> 6;
        int nl = lin & 63;
        sX[c][nl] = x[((b * C_ + c) * N_) + n0 + nl];
    }
    __syncthreads();

    const int tr = t & 15;
    const int tc = t >> 4;
    const int rb = 2 * tr;

    unsigned long long acc[4][4];
    #pragma unroll
    for (int i2 = 0; i2 < 4; i2++) {
        unsigned long long binit;
        if (i2 < 2) {
            const float2 bp = *(const float2*)&bias[rb + 32 * i2];
            binit = pack2(bp.x, bp.y);
        } else {
            binit = 0ull;
        }
        #pragma unroll
        for (int j = 0; j < 4; j++) acc[i2][j] = binit;
    }

    #pragma unroll 4
    for (int c = 0; c < 64; c++) {
        unsigned long long w2[4];
        #pragma unroll
        for (int i2 = 0; i2 < 4; i2++)
            w2[i2] = *(const unsigned long long*)&sW[c][rb + 32 * i2];  // LDS.64
        const float4 xq = *(const float4*)&sX[c][4 * tc];                // LDS.128
        unsigned long long x2[4];
        x2[0] = pack2(xq.x, xq.x);
        x2[1] = pack2(xq.y, xq.y);
        x2[2] = pack2(xq.z, xq.z);
        x2[3] = pack2(xq.w, xq.w);
        #pragma unroll
        for (int i2 = 0; i2 < 4; i2++)
            #pragma unroll
            for (int j = 0; j < 4; j++)
                ffma2(acc[i2][j], w2[i2], x2[j]);
    }

    __half* outb = g_uvh + (size_t)(b * N_ + n0) * R_;
    #pragma unroll
    for (int j = 0; j < 4; j++) {
        const int n = 4 * tc + j;
        #pragma unroll
        for (int i2 = 0; i2 < 4; i2++) {
            float lo, hi;
            unpack2(acc[i2][j], lo, hi);
            *(__half2*)(outb + n * R_ + rb + 32 * i2) = __floats2half2_rn(lo, hi);
        }
    }
}

// ---------------------------------------------------------------------------
// Kernel 2: out[b][o][n] = max_k relu( u[b][i1(k)][o] + v[b][i0(k)][o] )
// TWO nodes per warp: lanes 0-15 -> node A, 16-31 -> node B (adjacent).
//  - prologue: each lane loads its (i0,i1) pair (coalesced), packs (i1<<16)|i0
//  - per kk: 1 shfl + 2 extracts; 2x LDG.64 gathers (u-rows, v-rows) covering
//    both nodes; half2 add+max (4 channels/lane).
// ---------------------------------------------------------------------------
__global__ void __launch_bounds__(256) gather_max(const int* __restrict__ edge,
                                                  float* __restrict__ out) {
    __shared__ float sm[OUT_][17];   // 64 x 16 nodes, pad to 17

    const int b    = blockIdx.y;
    const int n0   = blockIdx.x * 16;
    const int w    = threadIdx.x >> 5;
    const int lane = threadIdx.x & 31;
    const int h    = lane >> 4;          // 0 = node A, 1 = node B
    const int sl   = lane & 15;          // sub-lane within node group
    const int n    = n0 + 2 * w + h;

    // Each lane loads both directions for (node n, k=sl). Coalesced 128B/warp per stream.
    const int e0 = edge[((0 * B_ + b) * N_ + n) * K_ + sl] & (N_ - 1);   // neighbor -> v
    const int e1 = edge[((1 * B_ + b) * N_ + n) * K_ + sl] & (N_ - 1);   // center   -> u
    const unsigned packed = (unsigned)e0 | ((unsigned)e1 << 16);

    const __half* uvb = g_uvh + (size_t)b * N_ * R_;
    const int co = 4 * sl;               // this lane's channel base (4 channels)

    __half2 m0 = __float2half2_rn(0.0f);
    __half2 m1 = __float2half2_rn(0.0f);

    #pragma unroll
    for (int kk = 0; kk < K_; kk++) {
        unsigned pk = __shfl_sync(0xffffffffu, packed, (h << 4) + kk);
        int i0 = (int)(pk & (unsigned)(N_ - 1));          // v source
        int i1 = (int)((pk >> 16) & (unsigned)(N_ - 1));  // u source
        uint2 uu = *(const uint2*)(uvb + i1 * R_ + co);         // u[co..co+3]
        uint2 vv = *(const uint2*)(uvb + i0 * R_ + 64 + co);    // v[co..co+3]
        __half2 ua = *(__half2*)&uu.x, ub = *(__half2*)&uu.y;
        __half2 va = *(__half2*)&vv.x, vb = *(__half2*)&vv.y;
        m0 = __hmax2(m0, __hadd2(ua, va));
        m1 = __hmax2(m1, __hadd2(ub, vb));
    }

    // Transpose through smem: lane owns channels co..co+3 of node_local nl.
    const int nl = 2 * w + h;
    float2 f0 = __half22float2(m0);
    float2 f1 = __half22float2(m1);
    sm[co + 0][nl] = f0.x;
    sm[co + 1][nl] = f0.y;
    sm[co + 2][nl] = f1.x;
    sm[co + 3][nl] = f1.y;
    __syncthreads();

    const int t = threadIdx.x;
    #pragma unroll
    for (int it = 0; it < 4; it++) {
        int lin = t + it * 256;          // 1024 values: 64 o x 16 n
        int o   = lin >> 4;
        int nn  = lin & 15;
        out[((b * OUT_ + o) * N_) + n0 + nn] = sm[o][nn];
    }
}

// ---------------------------------------------------------------------------
extern "C" void kernel_launch(void* const* d_in, const int* in_sizes, int n_in,
                              void* d_out, int out_size) {
    const float* x    = (const float*)d_in[0];
    const int*   edge = (const int*)d_in[1];
    const float* W    = (const float*)d_in[2];
    const float* bias = (const float*)d_in[3];
    float*       out  = (float*)d_out;

    cudaFuncSetAttribute(gemm_uv, cudaFuncAttributeMaxDynamicSharedMemorySize, SMEM_BYTES);

    dim3 g1(N_ / 64, B_);
    gemm_uv<<<g1, 256, SMEM_BYTES>>>(x, W, bias);

    dim3 g2(N_ / 16, B_);
    gather_max<<<g2, 256>>>(edge, out);
}

// round 7
// speedup vs baseline: 1.4662x; 1.0791x over previous
#include <cuda_runtime.h>
#include <cuda_fp16.h>

// Problem constants
#define B_    8
#define C_    64
#define N_    4096
#define K_    16
#define OUT_  64
#define R_    128   // 2*OUT rows: [0,64) = u (=(W1-W2)x + bias), [64,128) = v (=W2 x)

#define NT_   128   // nodes per block tile
#define SW_STRIDE 130   // even (8B-aligned pairs) and ≡2 mod 32 (≤2-way STS conflict)
#define SMEM_BYTES ((C_ * SW_STRIDE + C_ * NT_) * 4)   // 66,048 B

// Scratch (device global — no allocation allowed)
__device__ __half g_uvh[B_ * N_ * R_];   // [b][n][r] half: row = 256B = [u 0..63 | v 0..63]

// ---- packed f32x2 helpers (sm_100+ PTX) ------------------------------------
__device__ __forceinline__ unsigned long long pack2(float lo, float hi) {
    unsigned long long r;
    asm("mov.b64 %0, {%1, %2};" : "=l"(r) : "f"(lo), "f"(hi));
    return r;
}
__device__ __forceinline__ void unpack2(unsigned long long v, float& lo, float& hi) {
    asm("mov.b64 {%0, %1}, %2;" : "=f"(lo), "=f"(hi) : "l"(v));
}
__device__ __forceinline__ void ffma2(unsigned long long& d,
                                      unsigned long long a,
                                      unsigned long long b) {
    asm("fma.rn.f32x2 %0, %1, %2, %0;" : "+l"(d) : "l"(a), "l"(b));
}

// ---------------------------------------------------------------------------
// Kernel 1: uv[b][n][r] = sum_c Wt[c][r] * x[b][c][n] (+bias r<64), fp16 store.
// Tile 128r x 128n per block; thread computes 4 r-pairs x 8 nodes via FFMA2.
// Arithmetic intensity: 6 LDS feed 64 FMAs per iter -> FMA-pipe bound.
// ---------------------------------------------------------------------------
__global__ void __launch_bounds__(256) gemm_uv(const float* __restrict__ x,
                                               const float* __restrict__ W,
                                               const float* __restrict__ bias) {
    extern __shared__ float dsm[];
    float (*sW)[SW_STRIDE] = (float (*)[SW_STRIDE])dsm;          // [c][r] padded
    float (*sX)[NT_]       = (float (*)[NT_])(dsm + C_ * SW_STRIDE);

    const int b  = blockIdx.y;
    const int n0 = blockIdx.x * NT_;
    const int t  = threadIdx.x;

    // Fused weight transform (W is L2-resident after the first blocks).
    for (int lin = t; lin < C_ * OUT_; lin += 256) {
        int c = lin & 63;
        int r = lin >> 6;                 // 0..63
        float a  = W[r * 128 + c];        // W1[r][c]
        float bb = W[r * 128 + 64 + c];   // W2[r][c]
        sW[c][r]      = a - bb;
        sW[c][r + 64] = bb;
    }

    for (int lin = t; lin < C_ * NT_; lin += 256) {
        int c  = lin >> 7;
        int nl = lin & (NT_ - 1);
        sX[c][nl] = x[((b * C_ + c) * N_) + n0 + nl];
    }
    __syncthreads();

    const int tr = t & 15;
    const int tc = t >> 4;         // 0..15 -> nodes 8*tc .. 8*tc+7
    const int rb = 2 * tr;

    unsigned long long acc[4][8];
    #pragma unroll
    for (int i2 = 0; i2 < 4; i2++) {
        unsigned long long binit;
        if (i2 < 2) {
            const float2 bp = *(const float2*)&bias[rb + 32 * i2];
            binit = pack2(bp.x, bp.y);
        } else {
            binit = 0ull;
        }
        #pragma unroll
        for (int j = 0; j < 8; j++) acc[i2][j] = binit;
    }

    #pragma unroll 2
    for (int c = 0; c < 64; c++) {
        unsigned long long w2[4];
        #pragma unroll
        for (int i2 = 0; i2 < 4; i2++)
            w2[i2] = *(const unsigned long long*)&sW[c][rb + 32 * i2];  // LDS.64
        const float4 xa = *(const float4*)&sX[c][8 * tc];                // LDS.128
        const float4 xb = *(const float4*)&sX[c][8 * tc + 4];            // LDS.128
        unsigned long long x2[8];
        x2[0] = pack2(xa.x, xa.x);  x2[1] = pack2(xa.y, xa.y);
        x2[2] = pack2(xa.z, xa.z);  x2[3] = pack2(xa.w, xa.w);
        x2[4] = pack2(xb.x, xb.x);  x2[5] = pack2(xb.y, xb.y);
        x2[6] = pack2(xb.z, xb.z);  x2[7] = pack2(xb.w, xb.w);
        #pragma unroll
        for (int i2 = 0; i2 < 4; i2++)
            #pragma unroll
            for (int j = 0; j < 8; j++)
                ffma2(acc[i2][j], w2[i2], x2[j]);
    }

    __half* outb = g_uvh + (size_t)(b * N_ + n0) * R_;
    #pragma unroll
    for (int j = 0; j < 8; j++) {
        const int n = 8 * tc + j;
        #pragma unroll
        for (int i2 = 0; i2 < 4; i2++) {
            float lo, hi;
            unpack2(acc[i2][j], lo, hi);
            *(__half2*)(outb + n * R_ + rb + 32 * i2) = __floats2half2_rn(lo, hi);
        }
    }
}

// ---------------------------------------------------------------------------
// Kernel 2: out[b][o][n] = max_k relu( u[b][i1(k)][o] + v[b][i0(k)][o] )
// Two nodes per warp; packed-index shfl; LDG.64 gathers; half2 add/max.
// ---------------------------------------------------------------------------
__global__ void __launch_bounds__(256) gather_max(const int* __restrict__ edge,
                                                  float* __restrict__ out) {
    __shared__ float sm[OUT_][17];   // 64 x 16 nodes, pad to 17

    const int b    = blockIdx.y;
    const int n0   = blockIdx.x * 16;
    const int w    = threadIdx.x >> 5;
    const int lane = threadIdx.x & 31;
    const int h    = lane >> 4;          // 0 = node A, 1 = node B
    const int sl   = lane & 15;          // sub-lane within node group
    const int n    = n0 + 2 * w + h;

    const int e0 = edge[((0 * B_ + b) * N_ + n) * K_ + sl] & (N_ - 1);   // neighbor -> v
    const int e1 = edge[((1 * B_ + b) * N_ + n) * K_ + sl] & (N_ - 1);   // center   -> u
    const unsigned packed = (unsigned)e0 | ((unsigned)e1 << 16);

    const __half* uvb = g_uvh + (size_t)b * N_ * R_;
    const int co = 4 * sl;               // this lane's channel base (4 channels)

    __half2 m0 = __float2half2_rn(0.0f);
    __half2 m1 = __float2half2_rn(0.0f);

    #pragma unroll
    for (int kk = 0; kk < K_; kk++) {
        unsigned pk = __shfl_sync(0xffffffffu, packed, (h << 4) + kk);
        int i0 = (int)(pk & (unsigned)(N_ - 1));          // v source
        int i1 = (int)((pk >> 16) & (unsigned)(N_ - 1));  // u source
        uint2 uu = *(const uint2*)(uvb + i1 * R_ + co);         // u[co..co+3]
        uint2 vv = *(const uint2*)(uvb + i0 * R_ + 64 + co);    // v[co..co+3]
        __half2 ua = *(__half2*)&uu.x, ub = *(__half2*)&uu.y;
        __half2 va = *(__half2*)&vv.x, vb = *(__half2*)&vv.y;
        m0 = __hmax2(m0, __hadd2(ua, va));
        m1 = __hmax2(m1, __hadd2(ub, vb));
    }

    const int nl = 2 * w + h;
    float2 f0 = __half22float2(m0);
    float2 f1 = __half22float2(m1);
    sm[co + 0][nl] = f0.x;
    sm[co + 1][nl] = f0.y;
    sm[co + 2][nl] = f1.x;
    sm[co + 3][nl] = f1.y;
    __syncthreads();

    const int t = threadIdx.x;
    #pragma unroll
    for (int it = 0; it < 4; it++) {
        int lin = t + it * 256;          // 1024 values: 64 o x 16 n
        int o   = lin >> 4;
        int nn  = lin & 15;
        out[((b * OUT_ + o) * N_) + n0 + nn] = sm[o][nn];
    }
}

// ---------------------------------------------------------------------------
extern "C" void kernel_launch(void* const* d_in, const int* in_sizes, int n_in,
                              void* d_out, int out_size) {
    const float* x    = (const float*)d_in[0];
    const int*   edge = (const int*)d_in[1];
    const float* W    = (const float*)d_in[2];
    const float* bias = (const float*)d_in[3];
    float*       out  = (float*)d_out;

    cudaFuncSetAttribute(gemm_uv, cudaFuncAttributeMaxDynamicSharedMemorySize, SMEM_BYTES);

    dim3 g1(N_ / NT_, B_);
    gemm_uv<<<g1, 256, SMEM_BYTES>>>(x, W, bias);

    dim3 g2(N_ / 16, B_);
    gather_max<<<g2, 256>>>(edge, out);
}